// round 2
// baseline (speedup 1.0000x reference)
#include <cuda_runtime.h>
#include <cstddef>

// ---------------- compile-time Gaussian weights (win=11, sigma=1.5) ----------
// g[i] = exp(-(i-5)^2/4.5) / sum  — returned as literals after full unroll
__host__ __device__ __forceinline__ constexpr float gw(int t) {
    return (t == 0  || t == 10) ? 0.00102848f
         : (t == 1  || t == 9 ) ? 0.00759876f
         : (t == 2  || t == 8 ) ? 0.03600078f
         : (t == 3  || t == 7 ) ? 0.10936057f
         : (t == 4  || t == 6 ) ? 0.21300557f
         :                        0.26601165f;   // t == 5
}

#define TILE_W 32
#define TILE_H 64
#define IN_W   42          // TILE_W + 10
#define IN_H   74          // TILE_H + 10
#define XS_STRIDE 45       // padded: conflict-free for row/col strided access
#define HS_STRIDE 33       // padded: kills 8-way STS conflict in stage 1
#define NTHREADS 256

#define IMG_W 512
#define IMG_H 512
#define OUT_W 502
#define OUT_H 502
#define NCH   3

static constexpr float C1v = 6.5025f;    // (0.01*255)^2
static constexpr float C2v = 58.5225f;   // (0.03*255)^2

// dynamic smem layout (floats):
//   xs : IN_H * XS_STRIDE          (3330)
//   ys : IN_H * XS_STRIDE          (3330)
//   hs : 5 * IN_H * HS_STRIDE      (12210)
#define SMEM_FLOATS (2 * IN_H * XS_STRIDE + 5 * IN_H * HS_STRIDE)

__global__ void __launch_bounds__(NTHREADS)
ssim_kernel(const float* __restrict__ X, const float* __restrict__ Y,
            float* __restrict__ out)
{
    extern __shared__ float sm[];
    float* xs = sm;
    float* ys = xs + IN_H * XS_STRIDE;
    float* hs = ys + IN_H * XS_STRIDE;   // 5 fields, each IN_H*HS_STRIDE

    const int tid = threadIdx.x;
    const int tx  = blockIdx.x;          // 16 tiles of 32 cols
    const int ty  = blockIdx.y;          // 8 tiles of 64 rows
    const int n   = blockIdx.z;          // batch
    const int c0  = tx * TILE_W;
    const int r0  = ty * TILE_H;

    // stage-2 fixed decomposition: 32 cols x 8 row-groups = 256 tasks
    const int s2c  = tid & 31;
    const int s2rg = tid >> 5;

    float sacc[8];
#pragma unroll
    for (int j = 0; j < 8; j++) sacc[j] = 0.0f;

    for (int ch = 0; ch < NCH; ++ch) {
        const float* Xp = X + (size_t)(n * NCH + ch) * (IMG_W * IMG_H);
        const float* Yp = Y + (size_t)(n * NCH + ch) * (IMG_W * IMG_H);

        // ---- load input tiles (zero-fill out of bounds) ----
        for (int i = tid; i < IN_H * IN_W; i += NTHREADS) {
            int r = i / IN_W;
            int c = i - r * IN_W;
            int gr = r0 + r, gc = c0 + c;
            float xv = 0.0f, yv = 0.0f;
            if (gr < IMG_H && gc < IMG_W) {
                size_t o = (size_t)gr * IMG_W + gc;
                xv = Xp[o];
                yv = Yp[o];
            }
            xs[r * XS_STRIDE + c] = xv;
            ys[r * XS_STRIDE + c] = yv;
        }
        __syncthreads();

        // ---- stage 1: horizontal blur of 5 fields, row x 8-col runs ----
        for (int task = tid; task < IN_H * 4; task += NTHREADS) {
            int r  = task >> 2;
            int g8 = (task & 3) * 8;
            float a0[8], a1[8], a2[8], a3[8], a4[8];
#pragma unroll
            for (int j = 0; j < 8; j++) { a0[j]=a1[j]=a2[j]=a3[j]=a4[j]=0.0f; }

            const float* xr = xs + r * XS_STRIDE + g8;
            const float* yr = ys + r * XS_STRIDE + g8;
#pragma unroll
            for (int k = 0; k < 18; k++) {
                float x = xr[k], y = yr[k];
                float x2 = x * x, y2 = y * y, xy = x * y;
#pragma unroll
                for (int j = 0; j < 8; j++) {
                    const int t = k - j;
                    if (t >= 0 && t < 11) {
                        const float w = gw(t);      // literal after unroll -> FFMA-imm
                        a0[j] = fmaf(x,  w, a0[j]);
                        a1[j] = fmaf(y,  w, a1[j]);
                        a2[j] = fmaf(x2, w, a2[j]);
                        a3[j] = fmaf(y2, w, a3[j]);
                        a4[j] = fmaf(xy, w, a4[j]);
                    }
                }
            }
            float* h0 = hs + r * HS_STRIDE + g8;
#pragma unroll
            for (int j = 0; j < 8; j++) {
                h0[j]                          = a0[j];
                h0[1 * IN_H * HS_STRIDE + j]   = a1[j];
                h0[2 * IN_H * HS_STRIDE + j]   = a2[j];
                h0[3 * IN_H * HS_STRIDE + j]   = a3[j];
                h0[4 * IN_H * HS_STRIDE + j]   = a4[j];
            }
        }
        __syncthreads();

        // ---- stage 2: vertical blur + SSIM map, col x 8-row runs ----
        {
            float b0[8], b1[8], b2[8], b3[8], b4[8];
#pragma unroll
            for (int j = 0; j < 8; j++) { b0[j]=b1[j]=b2[j]=b3[j]=b4[j]=0.0f; }

            const float* h = hs + (s2rg * 8) * HS_STRIDE + s2c;
#pragma unroll
            for (int k = 0; k < 18; k++) {
                float v0 = h[k * HS_STRIDE];
                float v1 = h[1 * IN_H * HS_STRIDE + k * HS_STRIDE];
                float v2 = h[2 * IN_H * HS_STRIDE + k * HS_STRIDE];
                float v3 = h[3 * IN_H * HS_STRIDE + k * HS_STRIDE];
                float v4 = h[4 * IN_H * HS_STRIDE + k * HS_STRIDE];
#pragma unroll
                for (int j = 0; j < 8; j++) {
                    const int t = k - j;
                    if (t >= 0 && t < 11) {
                        const float w = gw(t);
                        b0[j] = fmaf(v0, w, b0[j]);
                        b1[j] = fmaf(v1, w, b1[j]);
                        b2[j] = fmaf(v2, w, b2[j]);
                        b3[j] = fmaf(v3, w, b3[j]);
                        b4[j] = fmaf(v4, w, b4[j]);
                    }
                }
            }
#pragma unroll
            for (int j = 0; j < 8; j++) {
                float mu1 = b0[j], mu2 = b1[j];
                float m11 = mu1 * mu1, m22 = mu2 * mu2, m12 = mu1 * mu2;
                float s1  = b2[j] - m11;
                float s2v = b3[j] - m22;
                float s12 = b4[j] - m12;
                float num = (2.0f * s12 + C2v) * (2.0f * m12 + C1v);
                float den = (s1 + s2v + C2v) * (m11 + m22 + C1v);
                sacc[j] += __fdividef(num, den);
            }
        }
        __syncthreads();   // before next channel overwrites xs/ys/hs
    }

    // ---- write: 1 - mean over channels ----
#pragma unroll
    for (int j = 0; j < 8; j++) {
        int oh = r0 + s2rg * 8 + j;
        int ow = c0 + s2c;
        if (oh < OUT_H && ow < OUT_W) {
            out[((size_t)n * OUT_H + oh) * OUT_W + ow] =
                1.0f - sacc[j] * (1.0f / 3.0f);
        }
    }
}

extern "C" void kernel_launch(void* const* d_in, const int* in_sizes, int n_in,
                              void* d_out, int out_size)
{
    const float* X = (const float*)d_in[0];
    const float* Y = (const float*)d_in[1];
    float* out = (float*)d_out;

    const int smem_bytes = SMEM_FLOATS * (int)sizeof(float);  // 75480
    cudaFuncSetAttribute(ssim_kernel,
                         cudaFuncAttributeMaxDynamicSharedMemorySize,
                         smem_bytes);

    dim3 grid((OUT_W + TILE_W - 1) / TILE_W,   // 16
              (OUT_H + TILE_H - 1) / TILE_H,   // 8
              16);                             // batch
    ssim_kernel<<<grid, NTHREADS, smem_bytes>>>(X, Y, out);
}

// round 4
// speedup vs baseline: 1.1690x; 1.1690x over previous
#include <cuda_runtime.h>
#include <cstddef>

// ---------------- compile-time Gaussian weights (win=11, sigma=1.5) ----------
__host__ __device__ __forceinline__ constexpr float gw(int t) {
    return (t == 0  || t == 10) ? 0.00102848f
         : (t == 1  || t == 9 ) ? 0.00759876f
         : (t == 2  || t == 8 ) ? 0.03600078f
         : (t == 3  || t == 7 ) ? 0.10936057f
         : (t == 4  || t == 6 ) ? 0.21300557f
         :                        0.26601165f;   // t == 5
}

#define TILE_W 32
#define TILE_H 64
#define IN_W   42          // TILE_W + 10
#define IN_H   74          // TILE_H + 10
#define NTHREADS 256

#define IMG_W 512
#define IMG_H 512
#define OUT_W 502
#define OUT_H 502
#define NCH   3

// xs: interleaved (x,y) pairs. 45 pairs/row (44 written by float4 loads + pad),
// row stride 90 floats: 8B-aligned rows, 26r mod 32 -> multiplicity 2 on LDS.64.
#define XS_STRIDE 90
// hs4: 4 fields interleaved per col (float4). 32 cols, row stride 132 floats:
// 16B-aligned rows, 4r mod 32 distinct for r0..7 -> conflict-free .128 access.
#define HS4_STRIDE 132
// hs1: 5th field scalar plane, row stride 33 (odd -> conflict-free).
#define HS1_STRIDE 33

static constexpr float C1v = 6.5025f;    // (0.01*255)^2
static constexpr float C2v = 58.5225f;   // (0.03*255)^2

// dynamic smem (floats): xs 74*90=6660, hs4 74*132=9768, hs1 74*33=2442
#define SMEM_FLOATS (IN_H * XS_STRIDE + IN_H * HS4_STRIDE + IN_H * HS1_STRIDE)

__global__ void __launch_bounds__(NTHREADS)
ssim_kernel(const float* __restrict__ X, const float* __restrict__ Y,
            float* __restrict__ out)
{
    extern __shared__ float sm[];
    float* xs  = sm;                                 // (x,y) interleaved
    float* hs4 = xs  + IN_H * XS_STRIDE;             // 4 fields interleaved
    float* hs1 = hs4 + IN_H * HS4_STRIDE;            // xy-blur plane

    const int tid = threadIdx.x;
    const int tx  = blockIdx.x;
    const int ty  = blockIdx.y;
    const int n   = blockIdx.z;
    const int c0  = tx * TILE_W;
    const int r0  = ty * TILE_H;

    const int s2c  = tid & 31;    // stage-2 column
    const int s2rg = tid >> 5;    // stage-2 row group (8 rows)

    float sacc[8];
#pragma unroll
    for (int j = 0; j < 8; j++) sacc[j] = 0.0f;

    for (int ch = 0; ch < NCH; ++ch) {
        const float* Xp = X + (size_t)(n * NCH + ch) * (IMG_W * IMG_H);
        const float* Yp = Y + (size_t)(n * NCH + ch) * (IMG_W * IMG_H);

        // ---- load: float4 global reads, (x,y)-pair smem writes ----
        // 74 rows x 11 float4-slots = 814 slots (covers cols 0..43)
        for (int i = tid; i < IN_H * 11; i += NTHREADS) {
            int r = i / 11;
            int f = i - r * 11;
            int gr = r0 + r;
            int gc = c0 + 4 * f;
            float4 x4 = make_float4(0.f, 0.f, 0.f, 0.f);
            float4 y4 = x4;
            if (gr < IMG_H && gc < IMG_W) {   // float4 fully in or fully out
                size_t o = (size_t)gr * IMG_W + gc;
                x4 = *reinterpret_cast<const float4*>(Xp + o);
                y4 = *reinterpret_cast<const float4*>(Yp + o);
            }
            float* p = xs + r * XS_STRIDE + 8 * f;
            *reinterpret_cast<float2*>(p + 0) = make_float2(x4.x, y4.x);
            *reinterpret_cast<float2*>(p + 2) = make_float2(x4.y, y4.y);
            *reinterpret_cast<float2*>(p + 4) = make_float2(x4.z, y4.z);
            *reinterpret_cast<float2*>(p + 6) = make_float2(x4.w, y4.w);
        }
        __syncthreads();

        // ---- stage 1: horizontal blur of 5 fields ----
        // task -> r = task % 74, g = task / 74  (lanes = consecutive rows)
        for (int task = tid; task < IN_H * 4; task += NTHREADS) {
            int g  = task / IN_H;
            int r  = task - g * IN_H;
            int g8 = g * 8;

            float a0[8], a1[8], a2[8], a3[8], a4[8];
#pragma unroll
            for (int j = 0; j < 8; j++) { a0[j]=a1[j]=a2[j]=a3[j]=a4[j]=0.0f; }

            const float* xr = xs + r * XS_STRIDE + 2 * g8;
#pragma unroll
            for (int k = 0; k < 18; k++) {
                float2 p = *reinterpret_cast<const float2*>(xr + 2 * k);
                float x = p.x, y = p.y;
                float x2 = x * x, y2 = y * y, xy = x * y;
#pragma unroll
                for (int j = 0; j < 8; j++) {
                    const int t = k - j;
                    if (t >= 0 && t < 11) {
                        const float w = gw(t);   // literal -> FFMA-imm
                        a0[j] = fmaf(x,  w, a0[j]);
                        a1[j] = fmaf(y,  w, a1[j]);
                        a2[j] = fmaf(x2, w, a2[j]);
                        a3[j] = fmaf(y2, w, a3[j]);
                        a4[j] = fmaf(xy, w, a4[j]);
                    }
                }
            }
            float* h4 = hs4 + r * HS4_STRIDE + 4 * g8;
            float* h1 = hs1 + r * HS1_STRIDE + g8;
#pragma unroll
            for (int j = 0; j < 8; j++) {
                *reinterpret_cast<float4*>(h4 + 4 * j) =
                    make_float4(a0[j], a1[j], a2[j], a3[j]);
                h1[j] = a4[j];
            }
        }
        __syncthreads();

        // ---- stage 2: vertical blur + SSIM map ----
        {
            float b0[8], b1[8], b2[8], b3[8], b4[8];
#pragma unroll
            for (int j = 0; j < 8; j++) { b0[j]=b1[j]=b2[j]=b3[j]=b4[j]=0.0f; }

            const float* h4 = hs4 + (s2rg * 8) * HS4_STRIDE + 4 * s2c;
            const float* h1 = hs1 + (s2rg * 8) * HS1_STRIDE + s2c;
#pragma unroll
            for (int k = 0; k < 18; k++) {
                float4 v = *reinterpret_cast<const float4*>(h4 + k * HS4_STRIDE);
                float v4 = h1[k * HS1_STRIDE];
#pragma unroll
                for (int j = 0; j < 8; j++) {
                    const int t = k - j;
                    if (t >= 0 && t < 11) {
                        const float w = gw(t);
                        b0[j] = fmaf(v.x, w, b0[j]);
                        b1[j] = fmaf(v.y, w, b1[j]);
                        b2[j] = fmaf(v.z, w, b2[j]);
                        b3[j] = fmaf(v.w, w, b3[j]);
                        b4[j] = fmaf(v4,  w, b4[j]);
                    }
                }
            }
#pragma unroll
            for (int j = 0; j < 8; j++) {
                float mu1 = b0[j], mu2 = b1[j];
                float m11 = mu1 * mu1, m22 = mu2 * mu2, m12 = mu1 * mu2;
                float s1  = b2[j] - m11;
                float s2v = b3[j] - m22;
                float s12 = b4[j] - m12;
                float num = (2.0f * s12 + C2v) * (2.0f * m12 + C1v);
                float den = (s1 + s2v + C2v) * (m11 + m22 + C1v);
                sacc[j] += __fdividef(num, den);
            }
        }
        __syncthreads();   // before next channel overwrites smem
    }

    // ---- write: 1 - mean over channels ----
#pragma unroll
    for (int j = 0; j < 8; j++) {
        int oh = r0 + s2rg * 8 + j;
        int ow = c0 + s2c;
        if (oh < OUT_H && ow < OUT_W) {
            out[((size_t)n * OUT_H + oh) * OUT_W + ow] =
                1.0f - sacc[j] * (1.0f / 3.0f);
        }
    }
}

extern "C" void kernel_launch(void* const* d_in, const int* in_sizes, int n_in,
                              void* d_out, int out_size)
{
    const float* X = (const float*)d_in[0];
    const float* Y = (const float*)d_in[1];
    float* out = (float*)d_out;

    const int smem_bytes = SMEM_FLOATS * (int)sizeof(float);  // 75480
    cudaFuncSetAttribute(ssim_kernel,
                         cudaFuncAttributeMaxDynamicSharedMemorySize,
                         smem_bytes);

    dim3 grid((OUT_W + TILE_W - 1) / TILE_W,   // 16
              (OUT_H + TILE_H - 1) / TILE_H,   // 8
              16);                             // batch
    ssim_kernel<<<grid, NTHREADS, smem_bytes>>>(X, Y, out);
}

// round 9
// speedup vs baseline: 1.2399x; 1.0607x over previous
#include <cuda_runtime.h>
#include <cstddef>
#include <cstdint>

// ---------------- compile-time Gaussian weights (win=11, sigma=1.5) ----------
__host__ __device__ __forceinline__ constexpr float gw(int t) {
    return (t == 0  || t == 10) ? 0.00102848f
         : (t == 1  || t == 9 ) ? 0.00759876f
         : (t == 2  || t == 8 ) ? 0.03600078f
         : (t == 3  || t == 7 ) ? 0.10936057f
         : (t == 4  || t == 6 ) ? 0.21300557f
         :                        0.26601165f;   // t == 5
}

// ---------------- packed f32x2 helpers (sm_100+) ----------------
__device__ __forceinline__ uint64_t bcast2(float w) {
    uint64_t r; asm("mov.b64 %0, {%1, %1};" : "=l"(r) : "f"(w)); return r;
}
__device__ __forceinline__ uint64_t pk2(float x, float y) {
    uint64_t r; asm("mov.b64 %0, {%1, %2};" : "=l"(r) : "f"(x), "f"(y)); return r;
}
__device__ __forceinline__ float2 unpk(uint64_t v) {
    float2 p; asm("mov.b64 {%0, %1}, %2;" : "=f"(p.x), "=f"(p.y) : "l"(v)); return p;
}
__device__ __forceinline__ void fma2(uint64_t& d, uint64_t a, uint64_t b) {
    asm("fma.rn.f32x2 %0, %1, %2, %0;" : "+l"(d) : "l"(a), "l"(b));
}
__device__ __forceinline__ uint64_t mul2(uint64_t a, uint64_t b) {
    uint64_t d; asm("mul.rn.f32x2 %0, %1, %2;" : "=l"(d) : "l"(a), "l"(b)); return d;
}

#define TILE_W 32
#define TILE_H 64
#define IN_W   42          // TILE_W + 10
#define IN_H   74          // TILE_H + 10
#define NTHREADS 256

#define IMG_W 512
#define IMG_H 512
#define OUT_W 502
#define OUT_H 502
#define NCH   3

#define XS_STRIDE 90       // (x,y) interleaved pairs, row stride in floats
#define HS4_STRIDE 132     // 4 fields interleaved (float4 per col), 16B-aligned rows
#define HS1_STRIDE 33      // xy-blur scalar plane, odd stride (scalar access only!)

static constexpr float C1v = 6.5025f;    // (0.01*255)^2
static constexpr float C2v = 58.5225f;   // (0.03*255)^2

#define SMEM_FLOATS (IN_H * XS_STRIDE + IN_H * HS4_STRIDE + IN_H * HS1_STRIDE)

__global__ void __launch_bounds__(NTHREADS, 3)
ssim_kernel(const float* __restrict__ X, const float* __restrict__ Y,
            float* __restrict__ out)
{
    extern __shared__ float sm[];
    float* xs  = sm;                                 // (x,y) interleaved
    float* hs4 = xs  + IN_H * XS_STRIDE;             // 4 fields interleaved
    float* hs1 = hs4 + IN_H * HS4_STRIDE;            // xy-blur plane

    const int tid = threadIdx.x;
    const int tx  = blockIdx.x;
    const int ty  = blockIdx.y;
    const int n   = blockIdx.z;
    const int c0  = tx * TILE_W;
    const int r0  = ty * TILE_H;

    const int s2c  = tid & 31;    // stage-2 column
    const int s2rg = tid >> 5;    // stage-2 row group (8 rows)

    // 6 broadcast weight pairs (symmetric kernel), hoisted into registers
    uint64_t ww[6];
#pragma unroll
    for (int t = 0; t < 6; t++) ww[t] = bcast2(gw(t));

    float sacc[8];
#pragma unroll
    for (int j = 0; j < 8; j++) sacc[j] = 0.0f;

    for (int ch = 0; ch < NCH; ++ch) {
        const float* Xp = X + (size_t)(n * NCH + ch) * (IMG_W * IMG_H);
        const float* Yp = Y + (size_t)(n * NCH + ch) * (IMG_W * IMG_H);

        // ---- load: float4 global reads, (x,y)-pair smem writes ----
        for (int i = tid; i < IN_H * 11; i += NTHREADS) {
            int r = i / 11;
            int f = i - r * 11;
            int gr = r0 + r;
            int gc = c0 + 4 * f;
            float4 x4 = make_float4(0.f, 0.f, 0.f, 0.f);
            float4 y4 = x4;
            if (gr < IMG_H && gc < IMG_W) {   // float4 fully in or fully out
                size_t o = (size_t)gr * IMG_W + gc;
                x4 = *reinterpret_cast<const float4*>(Xp + o);
                y4 = *reinterpret_cast<const float4*>(Yp + o);
            }
            float* p = xs + r * XS_STRIDE + 8 * f;
            *reinterpret_cast<float2*>(p + 0) = make_float2(x4.x, y4.x);
            *reinterpret_cast<float2*>(p + 2) = make_float2(x4.y, y4.y);
            *reinterpret_cast<float2*>(p + 4) = make_float2(x4.z, y4.z);
            *reinterpret_cast<float2*>(p + 6) = make_float2(x4.w, y4.w);
        }
        __syncthreads();

        // ---- stage 1: horizontal blur of 5 fields (f32x2-packed) ----
        for (int task = tid; task < IN_H * 4; task += NTHREADS) {
            int g  = task / IN_H;
            int r  = task - g * IN_H;
            int g8 = g * 8;

            uint64_t a01[8], a23[8];
            float a4[8];
#pragma unroll
            for (int j = 0; j < 8; j++) { a01[j] = 0ull; a23[j] = 0ull; a4[j] = 0.0f; }

            const float* xr = xs + r * XS_STRIDE + 2 * g8;
#pragma unroll
            for (int k = 0; k < 18; k++) {
                float2 p = *reinterpret_cast<const float2*>(xr + 2 * k);
                uint64_t xyp = pk2(p.x, p.y);        // (x, y)
                uint64_t sqp = mul2(xyp, xyp);       // (x^2, y^2)
                float xy = p.x * p.y;
#pragma unroll
                for (int j = 0; j < 8; j++) {
                    const int t = k - j;
                    if (t >= 0 && t < 11) {
                        const int tm = (t < 6) ? t : 10 - t;
                        fma2(a01[j], xyp, ww[tm]);   // blur(x), blur(y)
                        fma2(a23[j], sqp, ww[tm]);   // blur(x2), blur(y2)
                        a4[j] = fmaf(xy, gw(t), a4[j]);  // blur(xy), FFMA-imm
                    }
                }
            }
            float* h4 = hs4 + r * HS4_STRIDE + 4 * g8;
            float* h1 = hs1 + r * HS1_STRIDE + g8;
#pragma unroll
            for (int j = 0; j < 8; j++) {
                *reinterpret_cast<uint64_t*>(h4 + 4 * j)     = a01[j];
                *reinterpret_cast<uint64_t*>(h4 + 4 * j + 2) = a23[j];
                h1[j] = a4[j];   // scalar: hs1 stride is odd (alignment!)
            }
        }
        __syncthreads();

        // ---- stage 2: vertical blur (f32x2-packed) + SSIM map ----
        {
            uint64_t b01[8], b23[8];
            float b4[8];
#pragma unroll
            for (int j = 0; j < 8; j++) { b01[j] = 0ull; b23[j] = 0ull; b4[j] = 0.0f; }

            const float* h4 = hs4 + (s2rg * 8) * HS4_STRIDE + 4 * s2c;
            const float* h1 = hs1 + (s2rg * 8) * HS1_STRIDE + s2c;
#pragma unroll
            for (int k = 0; k < 18; k++) {
                ulonglong2 v = *reinterpret_cast<const ulonglong2*>(h4 + k * HS4_STRIDE);
                float v4 = h1[k * HS1_STRIDE];
#pragma unroll
                for (int j = 0; j < 8; j++) {
                    const int t = k - j;
                    if (t >= 0 && t < 11) {
                        const int tm = (t < 6) ? t : 10 - t;
                        fma2(b01[j], v.x, ww[tm]);   // mu1, mu2
                        fma2(b23[j], v.y, ww[tm]);   // blur(x2), blur(y2)
                        b4[j] = fmaf(v4, gw(t), b4[j]);
                    }
                }
            }
#pragma unroll
            for (int j = 0; j < 8; j++) {
                float2 mu  = unpk(b01[j]);               // mu1, mu2
                uint64_t msqp = mul2(b01[j], b01[j]);    // mu1^2, mu2^2
                float2 msq = unpk(msqp);
                float2 sg  = unpk(b23[j]);               // blur(x2), blur(y2)
                float m12 = mu.x * mu.y;
                float s1  = sg.x - msq.x;
                float s2v = sg.y - msq.y;
                float s12 = b4[j] - m12;
                float num = (2.0f * s12 + C2v) * (2.0f * m12 + C1v);
                float den = (s1 + s2v + C2v) * (msq.x + msq.y + C1v);
                sacc[j] += __fdividef(num, den);
            }
        }
        __syncthreads();   // before next channel overwrites smem
    }

    // ---- write: 1 - mean over channels ----
#pragma unroll
    for (int j = 0; j < 8; j++) {
        int oh = r0 + s2rg * 8 + j;
        int ow = c0 + s2c;
        if (oh < OUT_H && ow < OUT_W) {
            out[((size_t)n * OUT_H + oh) * OUT_W + ow] =
                1.0f - sacc[j] * (1.0f / 3.0f);
        }
    }
}

extern "C" void kernel_launch(void* const* d_in, const int* in_sizes, int n_in,
                              void* d_out, int out_size)
{
    const float* X = (const float*)d_in[0];
    const float* Y = (const float*)d_in[1];
    float* out = (float*)d_out;

    const int smem_bytes = SMEM_FLOATS * (int)sizeof(float);  // 75480
    cudaFuncSetAttribute(ssim_kernel,
                         cudaFuncAttributeMaxDynamicSharedMemorySize,
                         smem_bytes);

    dim3 grid((OUT_W + TILE_W - 1) / TILE_W,   // 16
              (OUT_H + TILE_H - 1) / TILE_H,   // 8
              16);                             // batch
    ssim_kernel<<<grid, NTHREADS, smem_bytes>>>(X, Y, out);
}